// round 11
// baseline (speedup 1.0000x reference)
#include <cuda_runtime.h>
#include <cuda_bf16.h>
#include <cstdint>

// ---------------------------------------------------------------------------
// Problem constants: B=4, L=8192, D=768, K=24, NFFT=16384.
// Math: out[t] = 2 * sum_{j even, j<=t} v[j] * u[t-j]
//   => two length-4096 causal convs with v_e[i]=v[2i], fused into ONE complex
//      FFT of size 8192 via z[k] = u[2k] + i*u[2k+1].
// GEMM u = x @ M_inputs runs as 3-pass bf16 split (AH*BH + AH*BL + AL*BH)
// with hi/lo planes precomputed once in global memory.
// ---------------------------------------------------------------------------

#define BATCH 4
#define SEQ   8192
#define DIM   768
#define NK    24
#define NC    8192
#define HALF  4096

#define SMX(i) ((i) + ((i) >> 4))
#define FFT_BUF 8704
#define FFT_SMEM_BYTES (2 * FFT_BUF * (int)sizeof(float2))   // 139264

// Scratch (device globals: no allocation allowed anywhere)
__device__ float    g_XT[(size_t)BATCH * DIM * SEQ];   // (B, D, L) fp32, in place
__device__ float2   g_VS[(size_t)DIM * NC];            // filter spectra
__device__ uint32_t g_AHw[(size_t)BATCH * SEQ * DIM / 2];  // x hi, bf16 pairs
__device__ uint32_t g_ALw[(size_t)BATCH * SEQ * DIM / 2];  // x lo
__device__ uint32_t g_BHw[(size_t)DIM * DIM / 2];          // Mi^T hi, [n][k] pairs
__device__ uint32_t g_BLw[(size_t)DIM * DIM / 2];          // Mi^T lo

// ---------------------------------------------------------------------------
// complex helpers
// ---------------------------------------------------------------------------
__device__ __forceinline__ float2 cmul(float2 a, float2 b) {
    return make_float2(a.x * b.x - a.y * b.y, a.x * b.y + a.y * b.x);
}

template<int DIR>
__device__ __forceinline__ void dft4(float2& a, float2& b, float2& c, float2& d) {
    float2 t0 = make_float2(a.x + c.x, a.y + c.y);
    float2 t1 = make_float2(a.x - c.x, a.y - c.y);
    float2 t2 = make_float2(b.x + d.x, b.y + d.y);
    float2 t3 = make_float2(b.x - d.x, b.y - d.y);
    a = make_float2(t0.x + t2.x, t0.y + t2.y);
    c = make_float2(t0.x - t2.x, t0.y - t2.y);
    if (DIR == -1) {
        b = make_float2(t1.x + t3.y, t1.y - t3.x);
        d = make_float2(t1.x - t3.y, t1.y + t3.x);
    } else {
        b = make_float2(t1.x - t3.y, t1.y + t3.x);
        d = make_float2(t1.x + t3.y, t1.y - t3.x);
    }
}

template<int DIR>
__device__ __forceinline__ void dft8(float2 v[8]) {
    const float S = 0.7071067811865476f;
    float2 e0 = v[0], e1 = v[2], e2 = v[4], e3 = v[6];
    float2 o0 = v[1], o1 = v[3], o2 = v[5], o3 = v[7];
    dft4<DIR>(e0, e1, e2, e3);
    dft4<DIR>(o0, o1, o2, o3);
    o1 = cmul(o1, make_float2(S, (float)DIR * S));
    o2 = (DIR == -1) ? make_float2(o2.y, -o2.x) : make_float2(-o2.y, o2.x);
    o3 = cmul(o3, make_float2(-S, (float)DIR * S));
    v[0] = make_float2(e0.x + o0.x, e0.y + o0.y); v[4] = make_float2(e0.x - o0.x, e0.y - o0.y);
    v[1] = make_float2(e1.x + o1.x, e1.y + o1.y); v[5] = make_float2(e1.x - o1.x, e1.y - o1.y);
    v[2] = make_float2(e2.x + o2.x, e2.y + o2.y); v[6] = make_float2(e2.x - o2.x, e2.y - o2.y);
    v[3] = make_float2(e3.x + o3.x, e3.y + o3.y); v[7] = make_float2(e3.x - o3.x, e3.y - o3.y);
}

template<int DIR>
__device__ __forceinline__ void fft8192(float2* src, float2* dst, int tid) {
    float2* s = src;
    float2* d = dst;
    int Ns = 1;
    #pragma unroll
    for (int st = 0; st < 4; st++) {
        const float angc = (float)DIR * 6.283185307179586f / (8.0f * (float)Ns);
        #pragma unroll
        for (int it = 0; it < 2; it++) {
            int j  = tid + it * 512;
            int jm = j & (Ns - 1);
            float ang = angc * (float)jm;
            float c, sn;
            __sincosf(ang, &sn, &c);
            float2 w1 = make_float2(c, sn);
            float2 v[8];
            v[0] = s[SMX(j)];
            float2 wr = w1;
            #pragma unroll
            for (int r = 1; r < 8; r++) {
                v[r] = cmul(s[SMX(j + r * 1024)], wr);
                wr = cmul(wr, w1);
            }
            dft8<DIR>(v);
            int base = ((j & ~(Ns - 1)) << 3) + jm;
            #pragma unroll
            for (int r = 0; r < 8; r++) d[SMX(base + r * Ns)] = v[r];
        }
        __syncthreads();
        float2* t = s; s = d; d = t;
        Ns <<= 3;
    }
    const float angc2 = (float)DIR * 6.283185307179586f / 8192.0f;
    #pragma unroll
    for (int it = 0; it < 8; it++) {
        int j = tid + it * 512;
        float c, sn;
        __sincosf(angc2 * (float)j, &sn, &c);
        float2 v0 = s[SMX(j)];
        float2 v1 = cmul(s[SMX(j + 4096)], make_float2(c, sn));
        d[SMX(j)]        = make_float2(v0.x + v1.x, v0.y + v1.y);
        d[SMX(j + 4096)] = make_float2(v0.x - v1.x, v0.y - v1.y);
    }
    __syncthreads();
}

// ---------------------------------------------------------------------------
// bf16 split helpers
// ---------------------------------------------------------------------------
__device__ __forceinline__ uint32_t pkbf(float lo, float hi) {
    uint32_t r;
    asm("cvt.rn.bf16x2.f32 %0, %1, %2;" : "=r"(r) : "f"(hi), "f"(lo));
    return r;
}
__device__ __forceinline__ float bfhi(float x) {
    return __bfloat162float(__float2bfloat16_rn(x));
}

// ---------------------------------------------------------------------------
// Pre-pass P1: split x -> AH/AL bf16 planes (row-major [m][k], k pairs packed)
// ---------------------------------------------------------------------------
__global__ void __launch_bounds__(256)
split_x_kernel(const float* __restrict__ X) {
    int i = blockIdx.x * 256 + threadIdx.x;    // float4 index
    float4 v = *(const float4*)(X + (size_t)i * 4);
    float h0 = bfhi(v.x), h1 = bfhi(v.y), h2 = bfhi(v.z), h3 = bfhi(v.w);
    g_AHw[(size_t)i * 2]     = pkbf(h0, h1);
    g_AHw[(size_t)i * 2 + 1] = pkbf(h2, h3);
    g_ALw[(size_t)i * 2]     = pkbf(v.x - h0, v.y - h1);
    g_ALw[(size_t)i * 2 + 1] = pkbf(v.z - h2, v.w - h3);
}

// ---------------------------------------------------------------------------
// Pre-pass P2: split + transpose Mi [k][n] -> BH/BL [n][k] bf16 pairs
// ---------------------------------------------------------------------------
__global__ void __launch_bounds__(256)
split_b_kernel(const float* __restrict__ Mi) {
    int idx = blockIdx.x * 256 + threadIdx.x;  // 768*384
    int n  = idx % DIM;
    int kp = idx / DIM;                        // k pair 0..383
    float v0 = Mi[(size_t)(2 * kp) * DIM + n];
    float v1 = Mi[(size_t)(2 * kp + 1) * DIM + n];
    float h0 = bfhi(v0), h1 = bfhi(v1);
    g_BHw[(size_t)n * (DIM / 2) + kp] = pkbf(h0, h1);
    g_BLw[(size_t)n * (DIM / 2) + kp] = pkbf(v0 - h0, v1 - h1);
}

// ---------------------------------------------------------------------------
// Kernel 1: filter prep. One CTA per output channel d.
// ---------------------------------------------------------------------------
__global__ void __launch_bounds__(512, 1)
filter_kernel(const float* __restrict__ phi, const float* __restrict__ Mf) {
    extern __shared__ float2 fb[];
    float2* A  = fb;
    float2* Bu = fb + FFT_BUF;
    __shared__ float mf[NK];

    const int tid = threadIdx.x;
    const int d   = blockIdx.x;
    if (tid < NK) mf[tid] = Mf[tid * DIM + d];
    __syncthreads();

    const float sc = 2.0f / 8192.0f;
    #pragma unroll 1
    for (int it = 0; it < 16; it++) {
        int i = tid + it * 512;
        float s = 0.0f;
        if (i < HALF) {
            const float* pr = phi + (size_t)i * (2 * NK);
            #pragma unroll
            for (int k = 0; k < NK; k++) s += pr[k] * mf[k];
        }
        A[SMX(i)] = make_float2(s * sc, 0.0f);
    }
    __syncthreads();

    fft8192<-1>(A, Bu, tid);

    float2* vsd = g_VS + ((size_t)d << 13);
    #pragma unroll 1
    for (int it = 0; it < 16; it++) {
        int i = tid + it * 512;
        vsd[i] = Bu[SMX(i)];
    }
}

// ---------------------------------------------------------------------------
// GEMM: pure bf16 pipelined kernel. CTA 128M x 256N, warp tile 64x64,
// 72 K-chunks of 32 (3 passes x 24), 4-stage cp.async ring, ldmatrix,
// 80B row pitch (conflict-free).
// ---------------------------------------------------------------------------
__device__ __forceinline__ uint32_t smem_u32(const void* p) {
    uint32_t a;
    asm("{ .reg .u64 t; cvta.to.shared.u64 t, %1; cvt.u32.u64 %0, t; }" : "=r"(a) : "l"(p));
    return a;
}
__device__ __forceinline__ void cpa16(uint32_t dst, const void* src) {
    asm volatile("cp.async.cg.shared.global [%0], [%1], 16;" :: "r"(dst), "l"(src));
}
__device__ __forceinline__ void ldsm4(uint32_t* r, uint32_t addr) {
    asm volatile("ldmatrix.sync.aligned.m8n8.x4.shared.b16 {%0,%1,%2,%3}, [%4];"
                 : "=r"(r[0]), "=r"(r[1]), "=r"(r[2]), "=r"(r[3]) : "r"(addr));
}
__device__ __forceinline__ void mma16(float4& d,
                                      uint32_t a0, uint32_t a1, uint32_t a2, uint32_t a3,
                                      uint32_t b0, uint32_t b1) {
    asm volatile(
        "mma.sync.aligned.m16n8k16.row.col.f32.bf16.bf16.f32 "
        "{%0,%1,%2,%3}, {%4,%5,%6,%7}, {%8,%9}, {%0,%1,%2,%3};"
        : "+f"(d.x), "+f"(d.y), "+f"(d.z), "+f"(d.w)
        : "r"(a0), "r"(a1), "r"(a2), "r"(a3), "r"(b0), "r"(b1));
}

#define APITCH 80                    // bytes per 32-k row (64B data + 16B pad)
#define A_STG  (128 * APITCH)        // 10240
#define B_STG  (256 * APITCH)        // 20480
#define STG_BYTES (A_STG + B_STG)    // 30720
#define GEMM_DYN_BYTES (4 * STG_BYTES)   // 122880
#define NCHUNK 72

// one thread's share of a chunk's cp.async: A 2x16B, B 4x16B (one full row)
__device__ __forceinline__ void gemm_issue(int c, uint32_t sbase, int tid,
                                           int l0, int n0) {
    int pass = c / 24;
    int kc   = c - pass * 24;
    const uint32_t* Aw = (pass < 2) ? g_AHw : g_ALw;
    const uint32_t* Bw = (pass == 1) ? g_BLw : g_BHw;
    uint32_t st = sbase + (uint32_t)(c & 3) * STG_BYTES;
    // A: 128 rows, 2 threads/row
    int arow = tid >> 1;
    int sg   = (tid & 1) * 2;
    const uint32_t* asrc = Aw + (size_t)(l0 + arow) * (DIM / 2) + kc * 16 + sg * 4;
    uint32_t adst = st + (uint32_t)(arow * APITCH + sg * 16);
    cpa16(adst, asrc);
    cpa16(adst + 16, asrc + 4);
    // B: 256 rows, 1 thread/row (64B)
    const uint32_t* bsrc = Bw + (size_t)(n0 + tid) * (DIM / 2) + kc * 16;
    uint32_t bdst = st + A_STG + (uint32_t)(tid * APITCH);
    cpa16(bdst,      bsrc);
    cpa16(bdst + 16, bsrc + 4);
    cpa16(bdst + 32, bsrc + 8);
    cpa16(bdst + 48, bsrc + 12);
    asm volatile("cp.async.commit_group;" ::: "memory");
}

__global__ void __launch_bounds__(256, 1)
gemm_kernel(int dummy) {
    extern __shared__ uint8_t smem_raw[];
    const uint32_t sbase = smem_u32(smem_raw);

    const int tid  = threadIdx.x;
    const int wid  = tid >> 5;
    const int lane = tid & 31;
    const int g    = lane >> 2;
    const int tig  = lane & 3;
    const int m0   = (wid & 1) * 64;      // warp m-half
    const int nw0  = (wid >> 1) * 64;     // warp n-quarter (64 cols)

    const int n0 = blockIdx.x * 256;
    const int l0 = blockIdx.y * 128;

    // prologue: fill 3 stages
    gemm_issue(0, sbase, tid, l0, n0);
    gemm_issue(1, sbase, tid, l0, n0);
    gemm_issue(2, sbase, tid, l0, n0);

    float4 acc[4][8];
    #pragma unroll
    for (int mt = 0; mt < 4; mt++)
        #pragma unroll
        for (int nt = 0; nt < 8; nt++)
            acc[mt][nt] = make_float4(0.f, 0.f, 0.f, 0.f);

    // fragment address components (stage-relative)
    const uint32_t aoff = (uint32_t)((m0 + (lane & 15)) * APITCH + (lane >> 4) * 16);
    const uint32_t boff = (uint32_t)(A_STG
                        + (nw0 + (lane & 7) + ((lane >> 4) << 3)) * APITCH
                        + ((lane >> 3) & 1) * 16);

    #pragma unroll 1
    for (int c = 0; c < NCHUNK; c++) {
        asm volatile("cp.async.wait_group 2;" ::: "memory");
        __syncthreads();
        if (c < NCHUNK - 3) gemm_issue(c + 3, sbase, tid, l0, n0);

        const uint32_t st = sbase + (uint32_t)(c & 3) * STG_BYTES;
        #pragma unroll
        for (int ks = 0; ks < 2; ks++) {
            uint32_t a[4][4];
            #pragma unroll
            for (int mt = 0; mt < 4; mt++)
                ldsm4(a[mt], st + aoff + (uint32_t)(mt * 16 * APITCH + ks * 32));
            uint32_t b[4][4];
            #pragma unroll
            for (int nh = 0; nh < 4; nh++)
                ldsm4(b[nh], st + boff + (uint32_t)(nh * 16 * APITCH + ks * 32));
            #pragma unroll
            for (int mt = 0; mt < 4; mt++)
                #pragma unroll
                for (int nt = 0; nt < 8; nt++)
                    mma16(acc[mt][nt], a[mt][0], a[mt][1], a[mt][2], a[mt][3],
                          b[nt >> 1][(nt & 1) * 2], b[nt >> 1][(nt & 1) * 2 + 1]);
        }
    }

    // epilogue: write transposed -> g_XT[b, d, l]
    const int b    = l0 >> 13;
    const int lloc = l0 & (SEQ - 1);
    #pragma unroll
    for (int mt = 0; mt < 4; mt++) {
        const int lbase = lloc + m0 + mt * 16 + g;
        #pragma unroll
        for (int nt = 0; nt < 8; nt++) {
            const int d0 = n0 + nw0 + nt * 8 + 2 * tig;
            float4 cc = acc[mt][nt];
            float* pa = g_XT + (((size_t)(b * DIM + d0)) << 13) + lbase;
            float* pb = g_XT + (((size_t)(b * DIM + d0 + 1)) << 13) + lbase;
            pa[0] = cc.x; pb[0] = cc.y;
            pa[8] = cc.z; pb[8] = cc.w;
        }
    }
}

// ---------------------------------------------------------------------------
// Kernel 3: per-(b,d) FFT convolution, in place on g_XT rows.
// ---------------------------------------------------------------------------
__global__ void __launch_bounds__(512, 1)
conv_kernel() {
    extern __shared__ float2 fb[];
    float2* A  = fb;
    float2* Bu = fb + FFT_BUF;

    const int tid = threadIdx.x;
    const int d   = blockIdx.x >> 2;
    const int b   = blockIdx.x & 3;

    float2* row = (float2*)(g_XT + (((size_t)(b * DIM + d)) << 13));

    #pragma unroll 1
    for (int it = 0; it < 16; it++) {
        int i = tid + it * 512;
        A[SMX(i)] = (i < HALF) ? row[i] : make_float2(0.0f, 0.0f);
    }
    __syncthreads();

    fft8192<-1>(A, Bu, tid);

    const float2* vs = g_VS + ((size_t)d << 13);
    #pragma unroll 1
    for (int it = 0; it < 16; it++) {
        int i = tid + it * 512;
        Bu[SMX(i)] = cmul(Bu[SMX(i)], vs[i]);
    }
    __syncthreads();

    fft8192<1>(Bu, A, tid);

    #pragma unroll 1
    for (int it = 0; it < 8; it++) {
        int i = tid + it * 512;
        row[i] = A[SMX(i)];                // (Re,Im) = (out[2m], out[2m+1])
    }
}

// ---------------------------------------------------------------------------
// Kernel 4: transpose g_XT (B,D,L) -> out (B,L,D)
// ---------------------------------------------------------------------------
__global__ void __launch_bounds__(256, 4)
transpose_kernel(float* __restrict__ out) {
    __shared__ float t[32][33];
    const int b  = blockIdx.z;
    const int l0 = blockIdx.x * 32;
    const int d0 = blockIdx.y * 32;
    const int tx = threadIdx.x, ty = threadIdx.y;   // 32 x 8

    const float* src = g_XT + (size_t)b * DIM * SEQ;
    #pragma unroll
    for (int i = 0; i < 4; i++)
        t[ty + i * 8][tx] = src[(size_t)(d0 + ty + i * 8) * SEQ + l0 + tx];
    __syncthreads();
    float* dst = out + (size_t)b * SEQ * DIM;
    #pragma unroll
    for (int i = 0; i < 4; i++)
        dst[(size_t)(l0 + ty + i * 8) * DIM + d0 + tx] = t[tx][ty + i * 8];
}

// ---------------------------------------------------------------------------
// launch
// ---------------------------------------------------------------------------
extern "C" void kernel_launch(void* const* d_in, const int* in_sizes, int n_in,
                              void* d_out, int out_size) {
    const float* x   = (const float*)d_in[0];
    const float* phi = (const float*)d_in[1];
    const float* Mi  = (const float*)d_in[2];
    const float* Mf  = (const float*)d_in[3];
    float* out = (float*)d_out;

    cudaFuncSetAttribute(filter_kernel, cudaFuncAttributeMaxDynamicSharedMemorySize, FFT_SMEM_BYTES);
    cudaFuncSetAttribute(conv_kernel,   cudaFuncAttributeMaxDynamicSharedMemorySize, FFT_SMEM_BYTES);
    cudaFuncSetAttribute(gemm_kernel,   cudaFuncAttributeMaxDynamicSharedMemorySize, GEMM_DYN_BYTES);

    split_x_kernel<<<(BATCH * SEQ * DIM / 4) / 256, 256>>>(x);
    split_b_kernel<<<(DIM * DIM / 2) / 256, 256>>>(Mi);
    filter_kernel<<<DIM, 512, FFT_SMEM_BYTES>>>(phi, Mf);
    gemm_kernel<<<dim3(DIM / 256, (BATCH * SEQ) / 128), 256, GEMM_DYN_BYTES>>>(0);
    conv_kernel<<<BATCH * DIM, 512, FFT_SMEM_BYTES>>>();
    transpose_kernel<<<dim3(SEQ / 32, DIM / 32, BATCH), dim3(32, 8)>>>(out);
}

// round 12
// speedup vs baseline: 1.3273x; 1.3273x over previous
#include <cuda_runtime.h>
#include <cuda_bf16.h>
#include <cstdint>

// ---------------------------------------------------------------------------
// Problem constants: B=4, L=8192, D=768, K=24, NFFT=16384.
// Math: out[t] = 2 * sum_{j even, j<=t} v[j] * u[t-j]
//   => two length-4096 causal convs with v_e[i]=v[2i], fused into ONE complex
//      FFT of size 8192 via z[k] = u[2k] + i*u[2k+1].
// GEMM u = x @ M_inputs runs as 3-pass bf16 split (AH*BH + AH*BL + AL*BH)
// with hi/lo planes precomputed once in global memory.
// ---------------------------------------------------------------------------

#define BATCH 4
#define SEQ   8192
#define DIM   768
#define NK    24
#define NC    8192
#define HALF  4096

#define SMX(i) ((i) + ((i) >> 4))
#define FFT_BUF 8704
#define FFT_SMEM_BYTES (2 * FFT_BUF * (int)sizeof(float2))   // 139264

// Scratch (device globals: no allocation allowed anywhere)
__device__ float    g_XT[(size_t)BATCH * DIM * SEQ];   // (B, D, L) fp32, in place
__device__ float2   g_VS[(size_t)DIM * NC];            // filter spectra
__device__ uint32_t g_AHw[(size_t)BATCH * SEQ * DIM / 2];  // x hi, bf16 pairs
__device__ uint32_t g_ALw[(size_t)BATCH * SEQ * DIM / 2];  // x lo
__device__ uint32_t g_BHw[(size_t)DIM * DIM / 2];          // Mi^T hi, [n][k] pairs
__device__ uint32_t g_BLw[(size_t)DIM * DIM / 2];          // Mi^T lo

// ---------------------------------------------------------------------------
// complex helpers
// ---------------------------------------------------------------------------
__device__ __forceinline__ float2 cmul(float2 a, float2 b) {
    return make_float2(a.x * b.x - a.y * b.y, a.x * b.y + a.y * b.x);
}

template<int DIR>
__device__ __forceinline__ void dft4(float2& a, float2& b, float2& c, float2& d) {
    float2 t0 = make_float2(a.x + c.x, a.y + c.y);
    float2 t1 = make_float2(a.x - c.x, a.y - c.y);
    float2 t2 = make_float2(b.x + d.x, b.y + d.y);
    float2 t3 = make_float2(b.x - d.x, b.y - d.y);
    a = make_float2(t0.x + t2.x, t0.y + t2.y);
    c = make_float2(t0.x - t2.x, t0.y - t2.y);
    if (DIR == -1) {
        b = make_float2(t1.x + t3.y, t1.y - t3.x);
        d = make_float2(t1.x - t3.y, t1.y + t3.x);
    } else {
        b = make_float2(t1.x - t3.y, t1.y + t3.x);
        d = make_float2(t1.x + t3.y, t1.y - t3.x);
    }
}

template<int DIR>
__device__ __forceinline__ void dft8(float2 v[8]) {
    const float S = 0.7071067811865476f;
    float2 e0 = v[0], e1 = v[2], e2 = v[4], e3 = v[6];
    float2 o0 = v[1], o1 = v[3], o2 = v[5], o3 = v[7];
    dft4<DIR>(e0, e1, e2, e3);
    dft4<DIR>(o0, o1, o2, o3);
    o1 = cmul(o1, make_float2(S, (float)DIR * S));
    o2 = (DIR == -1) ? make_float2(o2.y, -o2.x) : make_float2(-o2.y, o2.x);
    o3 = cmul(o3, make_float2(-S, (float)DIR * S));
    v[0] = make_float2(e0.x + o0.x, e0.y + o0.y); v[4] = make_float2(e0.x - o0.x, e0.y - o0.y);
    v[1] = make_float2(e1.x + o1.x, e1.y + o1.y); v[5] = make_float2(e1.x - o1.x, e1.y - o1.y);
    v[2] = make_float2(e2.x + o2.x, e2.y + o2.y); v[6] = make_float2(e2.x - o2.x, e2.y - o2.y);
    v[3] = make_float2(e3.x + o3.x, e3.y + o3.y); v[7] = make_float2(e3.x - o3.x, e3.y - o3.y);
}

// log-depth twiddle powers: p[r] = w1^(r+1) for r=0..6
template<int DIR>
__device__ __forceinline__ void twpow(float2 w1, float2 p[7]) {
    p[0] = w1;
    p[1] = cmul(w1, w1);          // w2
    p[2] = cmul(p[1], w1);        // w3
    p[3] = cmul(p[1], p[1]);      // w4
    p[4] = cmul(p[3], w1);        // w5
    p[5] = cmul(p[3], p[1]);      // w6
    p[6] = cmul(p[3], p[2]);      // w7
}

// generic radix-8 smem stage (Ns >= 8), ends with syncthreads
template<int DIR>
__device__ __forceinline__ void fft_stage(const float2* s, float2* d, int Ns, int tid) {
    const float angc = (float)DIR * 6.283185307179586f / (8.0f * (float)Ns);
    #pragma unroll
    for (int it = 0; it < 2; it++) {
        int j  = tid + it * 512;
        int jm = j & (Ns - 1);
        float c, sn;
        __sincosf(angc * (float)jm, &sn, &c);
        float2 p[7];
        twpow<DIR>(make_float2(c, sn), p);
        float2 v[8];
        v[0] = s[SMX(j)];
        #pragma unroll
        for (int r = 1; r < 8; r++) v[r] = cmul(s[SMX(j + r * 1024)], p[r - 1]);
        dft8<DIR>(v);
        int base = ((j & ~(Ns - 1)) << 3) + jm;
        #pragma unroll
        for (int r = 0; r < 8; r++) d[SMX(base + r * Ns)] = v[r];
    }
    __syncthreads();
}

// generic radix-2 final stage (Ns = 4096), smem->smem, ends with sync
template<int DIR>
__device__ __forceinline__ void fft_r2(const float2* s, float2* d, int tid) {
    const float angc2 = (float)DIR * 6.283185307179586f / 8192.0f;
    #pragma unroll
    for (int it = 0; it < 8; it++) {
        int j = tid + it * 512;
        float c, sn;
        __sincosf(angc2 * (float)j, &sn, &c);
        float2 v0 = s[SMX(j)];
        float2 v1 = cmul(s[SMX(j + 4096)], make_float2(c, sn));
        d[SMX(j)]        = make_float2(v0.x + v1.x, v0.y + v1.y);
        d[SMX(j + 4096)] = make_float2(v0.x - v1.x, v0.y - v1.y);
    }
    __syncthreads();
}

// full generic FFT (used by filter_kernel): src -> dst in smem
template<int DIR>
__device__ __forceinline__ void fft8192(float2* src, float2* dst, int tid) {
    // stage Ns=1 (no twiddles)
    #pragma unroll
    for (int it = 0; it < 2; it++) {
        int j = tid + it * 512;
        float2 v[8];
        #pragma unroll
        for (int r = 0; r < 8; r++) v[r] = src[SMX(j + r * 1024)];
        dft8<DIR>(v);
        #pragma unroll
        for (int r = 0; r < 8; r++) dst[SMX(j * 8 + r)] = v[r];
    }
    __syncthreads();
    fft_stage<DIR>(dst, src, 8, tid);
    fft_stage<DIR>(src, dst, 64, tid);
    fft_stage<DIR>(dst, src, 512, tid);
    fft_r2<DIR>(src, dst, tid);
}

// ---------------------------------------------------------------------------
// bf16 split helpers
// ---------------------------------------------------------------------------
__device__ __forceinline__ uint32_t pkbf(float lo, float hi) {
    uint32_t r;
    asm("cvt.rn.bf16x2.f32 %0, %1, %2;" : "=r"(r) : "f"(hi), "f"(lo));
    return r;
}
__device__ __forceinline__ float bfhi(float x) {
    return __bfloat162float(__float2bfloat16_rn(x));
}

// ---------------------------------------------------------------------------
// Pre-pass P1: split x -> AH/AL bf16 planes
// ---------------------------------------------------------------------------
__global__ void __launch_bounds__(256)
split_x_kernel(const float* __restrict__ X) {
    int i = blockIdx.x * 256 + threadIdx.x;
    float4 v = *(const float4*)(X + (size_t)i * 4);
    float h0 = bfhi(v.x), h1 = bfhi(v.y), h2 = bfhi(v.z), h3 = bfhi(v.w);
    g_AHw[(size_t)i * 2]     = pkbf(h0, h1);
    g_AHw[(size_t)i * 2 + 1] = pkbf(h2, h3);
    g_ALw[(size_t)i * 2]     = pkbf(v.x - h0, v.y - h1);
    g_ALw[(size_t)i * 2 + 1] = pkbf(v.z - h2, v.w - h3);
}

// ---------------------------------------------------------------------------
// Pre-pass P2: split + transpose Mi [k][n] -> BH/BL [n][k] bf16 pairs
// ---------------------------------------------------------------------------
__global__ void __launch_bounds__(256)
split_b_kernel(const float* __restrict__ Mi) {
    int idx = blockIdx.x * 256 + threadIdx.x;
    int n  = idx % DIM;
    int kp = idx / DIM;
    float v0 = Mi[(size_t)(2 * kp) * DIM + n];
    float v1 = Mi[(size_t)(2 * kp + 1) * DIM + n];
    float h0 = bfhi(v0), h1 = bfhi(v1);
    g_BHw[(size_t)n * (DIM / 2) + kp] = pkbf(h0, h1);
    g_BLw[(size_t)n * (DIM / 2) + kp] = pkbf(v0 - h0, v1 - h1);
}

// ---------------------------------------------------------------------------
// Kernel 1: filter prep. One CTA per output channel d.
// ---------------------------------------------------------------------------
__global__ void __launch_bounds__(512, 1)
filter_kernel(const float* __restrict__ phi, const float* __restrict__ Mf) {
    extern __shared__ float2 fb[];
    float2* A  = fb;
    float2* Bu = fb + FFT_BUF;
    __shared__ float mf[NK];

    const int tid = threadIdx.x;
    const int d   = blockIdx.x;
    if (tid < NK) mf[tid] = Mf[tid * DIM + d];
    __syncthreads();

    const float sc = 2.0f / 8192.0f;
    #pragma unroll 1
    for (int it = 0; it < 16; it++) {
        int i = tid + it * 512;
        float s = 0.0f;
        if (i < HALF) {
            const float* pr = phi + (size_t)i * (2 * NK);
            #pragma unroll
            for (int k = 0; k < NK; k++) s += pr[k] * mf[k];
        }
        A[SMX(i)] = make_float2(s * sc, 0.0f);
    }
    __syncthreads();

    fft8192<-1>(A, Bu, tid);

    float2* vsd = g_VS + ((size_t)d << 13);
    #pragma unroll 1
    for (int it = 0; it < 16; it++) {
        int i = tid + it * 512;
        vsd[i] = Bu[SMX(i)];
    }
}

// ---------------------------------------------------------------------------
// GEMM: pure bf16 pipelined kernel. CTA 128M x 128N, warp tile 64x32,
// K chunks of 64 (36 chunks = 3 passes x 12), 3-stage cp.async ring,
// ldmatrix, 144B row pitch (conflict-free). 2 CTAs/SM.
// ---------------------------------------------------------------------------
__device__ __forceinline__ uint32_t smem_u32(const void* p) {
    uint32_t a;
    asm("{ .reg .u64 t; cvta.to.shared.u64 t, %1; cvt.u32.u64 %0, t; }" : "=r"(a) : "l"(p));
    return a;
}
__device__ __forceinline__ void cpa16(uint32_t dst, const void* src) {
    asm volatile("cp.async.cg.shared.global [%0], [%1], 16;" :: "r"(dst), "l"(src));
}
__device__ __forceinline__ void ldsm4(uint32_t* r, uint32_t addr) {
    asm volatile("ldmatrix.sync.aligned.m8n8.x4.shared.b16 {%0,%1,%2,%3}, [%4];"
                 : "=r"(r[0]), "=r"(r[1]), "=r"(r[2]), "=r"(r[3]) : "r"(addr));
}
__device__ __forceinline__ void mma16(float4& d,
                                      uint32_t a0, uint32_t a1, uint32_t a2, uint32_t a3,
                                      uint32_t b0, uint32_t b1) {
    asm volatile(
        "mma.sync.aligned.m16n8k16.row.col.f32.bf16.bf16.f32 "
        "{%0,%1,%2,%3}, {%4,%5,%6,%7}, {%8,%9}, {%0,%1,%2,%3};"
        : "+f"(d.x), "+f"(d.y), "+f"(d.z), "+f"(d.w)
        : "r"(a0), "r"(a1), "r"(a2), "r"(a3), "r"(b0), "r"(b1));
}

#define APITCH 144                   // bytes per 64-k row (128B data + 16B pad)
#define A_STG  (128 * APITCH)        // 18432
#define STG_BYTES (2 * A_STG)        // 36864: A + B
#define GEMM_DYN_BYTES (3 * STG_BYTES)   // 110592, 3 stages
#define NCHUNK 36

// one thread's share of a chunk's cp.async: A 4x16B (half row), B 4x16B
__device__ __forceinline__ void gemm_issue(int c, uint32_t sbase, int tid,
                                           int l0, int n0) {
    int pass = c / 12;
    int kc   = c - pass * 12;
    const uint32_t* Aw = (pass < 2) ? g_AHw : g_ALw;
    const uint32_t* Bw = (pass == 1) ? g_BLw : g_BHw;
    uint32_t st = sbase + (uint32_t)(c % 3) * STG_BYTES;
    int row  = tid >> 1;
    int half = tid & 1;
    const uint32_t* asrc = Aw + (size_t)(l0 + row) * (DIM / 2) + kc * 32 + half * 16;
    uint32_t adst = st + (uint32_t)(row * APITCH + half * 64);
    cpa16(adst,      asrc);
    cpa16(adst + 16, asrc + 4);
    cpa16(adst + 32, asrc + 8);
    cpa16(adst + 48, asrc + 12);
    const uint32_t* bsrc = Bw + (size_t)(n0 + row) * (DIM / 2) + kc * 32 + half * 16;
    uint32_t bdst = st + A_STG + (uint32_t)(row * APITCH + half * 64);
    cpa16(bdst,      bsrc);
    cpa16(bdst + 16, bsrc + 4);
    cpa16(bdst + 32, bsrc + 8);
    cpa16(bdst + 48, bsrc + 12);
    asm volatile("cp.async.commit_group;" ::: "memory");
}

__global__ void __launch_bounds__(256, 2)
gemm_kernel(int dummy) {
    extern __shared__ uint8_t smem_raw[];
    const uint32_t sbase = smem_u32(smem_raw);

    const int tid  = threadIdx.x;
    const int wid  = tid >> 5;
    const int lane = tid & 31;
    const int g    = lane >> 2;
    const int tig  = lane & 3;
    const int m0   = (wid & 1) * 64;
    const int nw0  = (wid >> 1) * 32;

    const int n0 = blockIdx.x * 128;
    const int l0 = blockIdx.y * 128;

    // prologue: fill 2 stages
    gemm_issue(0, sbase, tid, l0, n0);
    gemm_issue(1, sbase, tid, l0, n0);

    float4 acc[4][4];
    #pragma unroll
    for (int mt = 0; mt < 4; mt++)
        #pragma unroll
        for (int nt = 0; nt < 4; nt++)
            acc[mt][nt] = make_float4(0.f, 0.f, 0.f, 0.f);

    const uint32_t aoff = (uint32_t)((m0 + (lane & 15)) * APITCH + (lane >> 4) * 16);
    const uint32_t boff = (uint32_t)(A_STG
                        + (nw0 + (lane & 7) + ((lane >> 4) << 3)) * APITCH
                        + ((lane >> 3) & 1) * 16);

    #pragma unroll 1
    for (int c = 0; c < NCHUNK; c++) {
        asm volatile("cp.async.wait_group 1;" ::: "memory");
        __syncthreads();
        if (c < NCHUNK - 2) gemm_issue(c + 2, sbase, tid, l0, n0);

        const uint32_t st = sbase + (uint32_t)(c % 3) * STG_BYTES;
        #pragma unroll
        for (int ks = 0; ks < 4; ks++) {
            uint32_t a[4][4];
            #pragma unroll
            for (int mt = 0; mt < 4; mt++)
                ldsm4(a[mt], st + aoff + (uint32_t)(mt * 16 * APITCH + ks * 32));
            uint32_t b[2][4];
            #pragma unroll
            for (int nh = 0; nh < 2; nh++)
                ldsm4(b[nh], st + boff + (uint32_t)(nh * 16 * APITCH + ks * 32));
            #pragma unroll
            for (int mt = 0; mt < 4; mt++)
                #pragma unroll
                for (int nt = 0; nt < 4; nt++)
                    mma16(acc[mt][nt], a[mt][0], a[mt][1], a[mt][2], a[mt][3],
                          b[nt >> 1][(nt & 1) * 2], b[nt >> 1][(nt & 1) * 2 + 1]);
        }
    }

    // epilogue: write transposed -> g_XT[b, d, l]
    const int b    = l0 >> 13;
    const int lloc = l0 & (SEQ - 1);
    #pragma unroll
    for (int mt = 0; mt < 4; mt++) {
        const int lbase = lloc + m0 + mt * 16 + g;
        #pragma unroll
        for (int nt = 0; nt < 4; nt++) {
            const int d0 = n0 + nw0 + nt * 8 + 2 * tig;
            float4 cc = acc[mt][nt];
            float* pa = g_XT + (((size_t)(b * DIM + d0)) << 13) + lbase;
            float* pb = g_XT + (((size_t)(b * DIM + d0 + 1)) << 13) + lbase;
            pa[0] = cc.x; pb[0] = cc.y;
            pa[8] = cc.z; pb[8] = cc.w;
        }
    }
}

// ---------------------------------------------------------------------------
// Kernel 3: per-(b,d) FFT convolution, in place on g_XT rows.
// Fused: fwd stage 1 reads global directly (zero-pad aware); inverse stage 1
// applies the spectral multiply; inverse final stage writes only the needed
// half straight to global.
// ---------------------------------------------------------------------------
__global__ void __launch_bounds__(512, 1)
conv_kernel() {
    extern __shared__ float2 fb[];
    float2* A  = fb;
    float2* Bu = fb + FFT_BUF;

    const int tid = threadIdx.x;
    const int d   = blockIdx.x >> 2;
    const int b   = blockIdx.x & 3;

    float2* row = (float2*)(g_XT + (((size_t)(b * DIM + d)) << 13));
    const float2* vs = g_VS + ((size_t)d << 13);

    // ---- forward FFT: stage 1 (Ns=1, no twiddle) straight from global ----
    #pragma unroll
    for (int it = 0; it < 2; it++) {
        int j = tid + it * 512;
        float2 v[8];
        #pragma unroll
        for (int r = 0; r < 8; r++)
            v[r] = (r < 4) ? row[j + r * 1024] : make_float2(0.0f, 0.0f);
        dft8<-1>(v);
        #pragma unroll
        for (int r = 0; r < 8; r++) A[SMX(j * 8 + r)] = v[r];
    }
    __syncthreads();
    fft_stage<-1>(A, Bu, 8, tid);
    fft_stage<-1>(Bu, A, 64, tid);
    fft_stage<-1>(A, Bu, 512, tid);
    fft_r2<-1>(Bu, A, tid);            // spectrum now in A

    // ---- inverse FFT: stage 1 (Ns=1) with fused spectral multiply ----
    #pragma unroll
    for (int it = 0; it < 2; it++) {
        int j = tid + it * 512;
        float2 v[8];
        #pragma unroll
        for (int r = 0; r < 8; r++) {
            int idx = j + r * 1024;
            v[r] = cmul(A[SMX(idx)], vs[idx]);
        }
        dft8<1>(v);
        #pragma unroll
        for (int r = 0; r < 8; r++) Bu[SMX(j * 8 + r)] = v[r];
    }
    __syncthreads();
    fft_stage<1>(Bu, A, 8, tid);
    fft_stage<1>(A, Bu, 64, tid);
    fft_stage<1>(Bu, A, 512, tid);

    // ---- inverse final radix-2: write the needed half straight to global ----
    const float angc2 = 6.283185307179586f / 8192.0f;
    #pragma unroll
    for (int it = 0; it < 8; it++) {
        int j = tid + it * 512;            // 0..4095
        float c, sn;
        __sincosf(angc2 * (float)j, &sn, &c);
        float2 v0 = A[SMX(j)];
        float2 v1 = cmul(A[SMX(j + 4096)], make_float2(c, sn));
        row[j] = make_float2(v0.x + v1.x, v0.y + v1.y);
    }
}

// ---------------------------------------------------------------------------
// Kernel 4: transpose g_XT (B,D,L) -> out (B,L,D)
// ---------------------------------------------------------------------------
__global__ void __launch_bounds__(256, 4)
transpose_kernel(float* __restrict__ out) {
    __shared__ float t[32][33];
    const int b  = blockIdx.z;
    const int l0 = blockIdx.x * 32;
    const int d0 = blockIdx.y * 32;
    const int tx = threadIdx.x, ty = threadIdx.y;   // 32 x 8

    const float* src = g_XT + (size_t)b * DIM * SEQ;
    #pragma unroll
    for (int i = 0; i < 4; i++)
        t[ty + i * 8][tx] = src[(size_t)(d0 + ty + i * 8) * SEQ + l0 + tx];
    __syncthreads();
    float* dst = out + (size_t)b * SEQ * DIM;
    #pragma unroll
    for (int i = 0; i < 4; i++)
        dst[(size_t)(l0 + ty + i * 8) * DIM + d0 + tx] = t[tx][ty + i * 8];
}

// ---------------------------------------------------------------------------
// launch
// ---------------------------------------------------------------------------
extern "C" void kernel_launch(void* const* d_in, const int* in_sizes, int n_in,
                              void* d_out, int out_size) {
    const float* x   = (const float*)d_in[0];
    const float* phi = (const float*)d_in[1];
    const float* Mi  = (const float*)d_in[2];
    const float* Mf  = (const float*)d_in[3];
    float* out = (float*)d_out;

    cudaFuncSetAttribute(filter_kernel, cudaFuncAttributeMaxDynamicSharedMemorySize, FFT_SMEM_BYTES);
    cudaFuncSetAttribute(conv_kernel,   cudaFuncAttributeMaxDynamicSharedMemorySize, FFT_SMEM_BYTES);
    cudaFuncSetAttribute(gemm_kernel,   cudaFuncAttributeMaxDynamicSharedMemorySize, GEMM_DYN_BYTES);

    split_x_kernel<<<(BATCH * SEQ * DIM / 4) / 256, 256>>>(x);
    split_b_kernel<<<(DIM * DIM / 2) / 256, 256>>>(Mi);
    filter_kernel<<<DIM, 512, FFT_SMEM_BYTES>>>(phi, Mf);
    gemm_kernel<<<dim3(DIM / 128, (BATCH * SEQ) / 128), 256, GEMM_DYN_BYTES>>>(0);
    conv_kernel<<<BATCH * DIM, 512, FFT_SMEM_BYTES>>>();
    transpose_kernel<<<dim3(SEQ / 32, DIM / 32, BATCH), dim3(32, 8)>>>(out);
}

// round 13
// speedup vs baseline: 1.5453x; 1.1642x over previous
#include <cuda_runtime.h>
#include <cuda_bf16.h>
#include <cstdint>

// ---------------------------------------------------------------------------
// Problem constants: B=4, L=8192, D=768, K=24, NFFT=16384.
// Math: out[t] = 2 * sum_{j even, j<=t} v[j] * u[t-j]
//   => two length-4096 causal convs with v_e[i]=v[2i], fused into ONE complex
//      FFT of size 8192 via z[k] = u[2k] + i*u[2k+1].
// GEMM u = x @ M_inputs: 3-term bf16 split (AH*BH + AH*BL + AL*BH), all three
// terms fused into a single k-sweep with 4 operand planes per stage.
// ---------------------------------------------------------------------------

#define BATCH 4
#define SEQ   8192
#define DIM   768
#define NK    24
#define NC    8192
#define HALF  4096

#define SMX(i) ((i) + ((i) >> 4))
#define FFT_BUF 8704
#define FFT_SMEM_BYTES (2 * FFT_BUF * (int)sizeof(float2))   // 139264

// Scratch (device globals: no allocation allowed anywhere)
__device__ float    g_XT[(size_t)BATCH * DIM * SEQ];   // (B, D, L) fp32, in place
__device__ float2   g_VS[(size_t)DIM * NC];            // filter spectra
__device__ uint32_t g_AHw[(size_t)BATCH * SEQ * DIM / 2];  // x hi, bf16 pairs
__device__ uint32_t g_ALw[(size_t)BATCH * SEQ * DIM / 2];  // x lo
__device__ uint32_t g_BHw[(size_t)DIM * DIM / 2];          // Mi^T hi, [n][k] pairs
__device__ uint32_t g_BLw[(size_t)DIM * DIM / 2];          // Mi^T lo

// ---------------------------------------------------------------------------
// complex helpers
// ---------------------------------------------------------------------------
__device__ __forceinline__ float2 cmul(float2 a, float2 b) {
    return make_float2(a.x * b.x - a.y * b.y, a.x * b.y + a.y * b.x);
}

template<int DIR>
__device__ __forceinline__ void dft4(float2& a, float2& b, float2& c, float2& d) {
    float2 t0 = make_float2(a.x + c.x, a.y + c.y);
    float2 t1 = make_float2(a.x - c.x, a.y - c.y);
    float2 t2 = make_float2(b.x + d.x, b.y + d.y);
    float2 t3 = make_float2(b.x - d.x, b.y - d.y);
    a = make_float2(t0.x + t2.x, t0.y + t2.y);
    c = make_float2(t0.x - t2.x, t0.y - t2.y);
    if (DIR == -1) {
        b = make_float2(t1.x + t3.y, t1.y - t3.x);
        d = make_float2(t1.x - t3.y, t1.y + t3.x);
    } else {
        b = make_float2(t1.x - t3.y, t1.y + t3.x);
        d = make_float2(t1.x + t3.y, t1.y - t3.x);
    }
}

template<int DIR>
__device__ __forceinline__ void dft8(float2 v[8]) {
    const float S = 0.7071067811865476f;
    float2 e0 = v[0], e1 = v[2], e2 = v[4], e3 = v[6];
    float2 o0 = v[1], o1 = v[3], o2 = v[5], o3 = v[7];
    dft4<DIR>(e0, e1, e2, e3);
    dft4<DIR>(o0, o1, o2, o3);
    o1 = cmul(o1, make_float2(S, (float)DIR * S));
    o2 = (DIR == -1) ? make_float2(o2.y, -o2.x) : make_float2(-o2.y, o2.x);
    o3 = cmul(o3, make_float2(-S, (float)DIR * S));
    v[0] = make_float2(e0.x + o0.x, e0.y + o0.y); v[4] = make_float2(e0.x - o0.x, e0.y - o0.y);
    v[1] = make_float2(e1.x + o1.x, e1.y + o1.y); v[5] = make_float2(e1.x - o1.x, e1.y - o1.y);
    v[2] = make_float2(e2.x + o2.x, e2.y + o2.y); v[6] = make_float2(e2.x - o2.x, e2.y - o2.y);
    v[3] = make_float2(e3.x + o3.x, e3.y + o3.y); v[7] = make_float2(e3.x - o3.x, e3.y - o3.y);
}

// log-depth twiddle powers: p[r] = w1^(r+1) for r=0..6
template<int DIR>
__device__ __forceinline__ void twpow(float2 w1, float2 p[7]) {
    p[0] = w1;
    p[1] = cmul(w1, w1);
    p[2] = cmul(p[1], w1);
    p[3] = cmul(p[1], p[1]);
    p[4] = cmul(p[3], w1);
    p[5] = cmul(p[3], p[1]);
    p[6] = cmul(p[3], p[2]);
}

// generic radix-8 smem stage (Ns >= 8), ends with syncthreads
template<int DIR>
__device__ __forceinline__ void fft_stage(const float2* s, float2* d, int Ns, int tid) {
    const float angc = (float)DIR * 6.283185307179586f / (8.0f * (float)Ns);
    #pragma unroll
    for (int it = 0; it < 2; it++) {
        int j  = tid + it * 512;
        int jm = j & (Ns - 1);
        float c, sn;
        __sincosf(angc * (float)jm, &sn, &c);
        float2 p[7];
        twpow<DIR>(make_float2(c, sn), p);
        float2 v[8];
        v[0] = s[SMX(j)];
        #pragma unroll
        for (int r = 1; r < 8; r++) v[r] = cmul(s[SMX(j + r * 1024)], p[r - 1]);
        dft8<DIR>(v);
        int base = ((j & ~(Ns - 1)) << 3) + jm;
        #pragma unroll
        for (int r = 0; r < 8; r++) d[SMX(base + r * Ns)] = v[r];
    }
    __syncthreads();
}

// generic radix-2 final stage (Ns = 4096), smem->smem, ends with sync
template<int DIR>
__device__ __forceinline__ void fft_r2(const float2* s, float2* d, int tid) {
    const float angc2 = (float)DIR * 6.283185307179586f / 8192.0f;
    #pragma unroll
    for (int it = 0; it < 8; it++) {
        int j = tid + it * 512;
        float c, sn;
        __sincosf(angc2 * (float)j, &sn, &c);
        float2 v0 = s[SMX(j)];
        float2 v1 = cmul(s[SMX(j + 4096)], make_float2(c, sn));
        d[SMX(j)]        = make_float2(v0.x + v1.x, v0.y + v1.y);
        d[SMX(j + 4096)] = make_float2(v0.x - v1.x, v0.y - v1.y);
    }
    __syncthreads();
}

// full generic FFT (used by filter_kernel): src -> dst in smem
template<int DIR>
__device__ __forceinline__ void fft8192(float2* src, float2* dst, int tid) {
    #pragma unroll
    for (int it = 0; it < 2; it++) {
        int j = tid + it * 512;
        float2 v[8];
        #pragma unroll
        for (int r = 0; r < 8; r++) v[r] = src[SMX(j + r * 1024)];
        dft8<DIR>(v);
        #pragma unroll
        for (int r = 0; r < 8; r++) dst[SMX(j * 8 + r)] = v[r];
    }
    __syncthreads();
    fft_stage<DIR>(dst, src, 8, tid);
    fft_stage<DIR>(src, dst, 64, tid);
    fft_stage<DIR>(dst, src, 512, tid);
    fft_r2<DIR>(src, dst, tid);
}

// ---------------------------------------------------------------------------
// bf16 split helpers
// ---------------------------------------------------------------------------
__device__ __forceinline__ uint32_t pkbf(float lo, float hi) {
    uint32_t r;
    asm("cvt.rn.bf16x2.f32 %0, %1, %2;" : "=r"(r) : "f"(hi), "f"(lo));
    return r;
}
__device__ __forceinline__ float bfhi(float x) {
    return __bfloat162float(__float2bfloat16_rn(x));
}

// ---------------------------------------------------------------------------
// Pre-pass P1: split x -> AH/AL bf16 planes
// ---------------------------------------------------------------------------
__global__ void __launch_bounds__(256)
split_x_kernel(const float* __restrict__ X) {
    int i = blockIdx.x * 256 + threadIdx.x;
    float4 v = *(const float4*)(X + (size_t)i * 4);
    float h0 = bfhi(v.x), h1 = bfhi(v.y), h2 = bfhi(v.z), h3 = bfhi(v.w);
    g_AHw[(size_t)i * 2]     = pkbf(h0, h1);
    g_AHw[(size_t)i * 2 + 1] = pkbf(h2, h3);
    g_ALw[(size_t)i * 2]     = pkbf(v.x - h0, v.y - h1);
    g_ALw[(size_t)i * 2 + 1] = pkbf(v.z - h2, v.w - h3);
}

// ---------------------------------------------------------------------------
// Pre-pass P2: split + transpose Mi [k][n] -> BH/BL [n][k] bf16 pairs
// ---------------------------------------------------------------------------
__global__ void __launch_bounds__(256)
split_b_kernel(const float* __restrict__ Mi) {
    int idx = blockIdx.x * 256 + threadIdx.x;
    int n  = idx % DIM;
    int kp = idx / DIM;
    float v0 = Mi[(size_t)(2 * kp) * DIM + n];
    float v1 = Mi[(size_t)(2 * kp + 1) * DIM + n];
    float h0 = bfhi(v0), h1 = bfhi(v1);
    g_BHw[(size_t)n * (DIM / 2) + kp] = pkbf(h0, h1);
    g_BLw[(size_t)n * (DIM / 2) + kp] = pkbf(v0 - h0, v1 - h1);
}

// ---------------------------------------------------------------------------
// Kernel 1: filter prep. One CTA per output channel d.
// ---------------------------------------------------------------------------
__global__ void __launch_bounds__(512, 1)
filter_kernel(const float* __restrict__ phi, const float* __restrict__ Mf) {
    extern __shared__ float2 fb[];
    float2* A  = fb;
    float2* Bu = fb + FFT_BUF;
    __shared__ float mf[NK];

    const int tid = threadIdx.x;
    const int d   = blockIdx.x;
    if (tid < NK) mf[tid] = Mf[tid * DIM + d];
    __syncthreads();

    const float sc = 2.0f / 8192.0f;
    #pragma unroll 1
    for (int it = 0; it < 16; it++) {
        int i = tid + it * 512;
        float s = 0.0f;
        if (i < HALF) {
            const float* pr = phi + (size_t)i * (2 * NK);
            #pragma unroll
            for (int k = 0; k < NK; k++) s += pr[k] * mf[k];
        }
        A[SMX(i)] = make_float2(s * sc, 0.0f);
    }
    __syncthreads();

    fft8192<-1>(A, Bu, tid);

    float2* vsd = g_VS + ((size_t)d << 13);
    #pragma unroll 1
    for (int it = 0; it < 16; it++) {
        int i = tid + it * 512;
        vsd[i] = Bu[SMX(i)];
    }
}

// ---------------------------------------------------------------------------
// GEMM: fused 3-term bf16 kernel. CTA 128M x 128N, warp tile 64x32,
// 24 K-chunks of 32; each stage holds 4 planes (AH, AL, BH, BL) of 8KB,
// APITCH=80 (conflict-free ldmatrix). 2-stage cp.async ring, 2 CTAs/SM.
// Per chunk: pass1 aH*bH, pass2 aH*bL, pass3 aL*bH (fragment reuse).
// ---------------------------------------------------------------------------
__device__ __forceinline__ uint32_t smem_u32(const void* p) {
    uint32_t a;
    asm("{ .reg .u64 t; cvta.to.shared.u64 t, %1; cvt.u32.u64 %0, t; }" : "=r"(a) : "l"(p));
    return a;
}
__device__ __forceinline__ void cpa16(uint32_t dst, const void* src) {
    asm volatile("cp.async.cg.shared.global [%0], [%1], 16;" :: "r"(dst), "l"(src));
}
__device__ __forceinline__ void ldsm4(uint32_t* r, uint32_t addr) {
    asm volatile("ldmatrix.sync.aligned.m8n8.x4.shared.b16 {%0,%1,%2,%3}, [%4];"
                 : "=r"(r[0]), "=r"(r[1]), "=r"(r[2]), "=r"(r[3]) : "r"(addr));
}
__device__ __forceinline__ void mma16(float4& d,
                                      uint32_t a0, uint32_t a1, uint32_t a2, uint32_t a3,
                                      uint32_t b0, uint32_t b1) {
    asm volatile(
        "mma.sync.aligned.m16n8k16.row.col.f32.bf16.bf16.f32 "
        "{%0,%1,%2,%3}, {%4,%5,%6,%7}, {%8,%9}, {%0,%1,%2,%3};"
        : "+f"(d.x), "+f"(d.y), "+f"(d.z), "+f"(d.w)
        : "r"(a0), "r"(a1), "r"(a2), "r"(a3), "r"(b0), "r"(b1));
}

#define APITCH 80                    // bytes per 32-k row (64B data + 16B pad)
#define PLANE  (128 * APITCH)        // 10240 per plane
#define STG_BYTES (4 * PLANE)        // 40960: AH, AL, BH, BL
#define GEMM_DYN_BYTES (2 * STG_BYTES)   // 81920, 2 stages
#define NCHUNK 24

// one thread's share of a chunk: 2x16B for each of the 4 planes
__device__ __forceinline__ void gemm_issue(int kc, uint32_t sbase, int tid,
                                           int l0, int n0) {
    uint32_t st = sbase + (uint32_t)(kc & 1) * STG_BYTES;
    int row  = tid >> 1;
    int half = tid & 1;
    size_t aoffg = (size_t)(l0 + row) * (DIM / 2) + kc * 16 + half * 8;
    size_t boffg = (size_t)(n0 + row) * (DIM / 2) + kc * 16 + half * 8;
    uint32_t dst = st + (uint32_t)(row * APITCH + half * 32);
    cpa16(dst,                  g_AHw + aoffg);
    cpa16(dst + 16,             g_AHw + aoffg + 4);
    cpa16(dst + PLANE,          g_ALw + aoffg);
    cpa16(dst + PLANE + 16,     g_ALw + aoffg + 4);
    cpa16(dst + 2 * PLANE,      g_BHw + boffg);
    cpa16(dst + 2 * PLANE + 16, g_BHw + boffg + 4);
    cpa16(dst + 3 * PLANE,      g_BLw + boffg);
    cpa16(dst + 3 * PLANE + 16, g_BLw + boffg + 4);
    asm volatile("cp.async.commit_group;" ::: "memory");
}

__global__ void __launch_bounds__(256, 2)
gemm_kernel(int dummy) {
    extern __shared__ uint8_t smem_raw[];
    const uint32_t sbase = smem_u32(smem_raw);

    const int tid  = threadIdx.x;
    const int wid  = tid >> 5;
    const int lane = tid & 31;
    const int g    = lane >> 2;
    const int tig  = lane & 3;
    const int m0   = (wid & 1) * 64;
    const int nw0  = (wid >> 1) * 32;

    const int n0 = blockIdx.x * 128;
    const int l0 = blockIdx.y * 128;

    // prologue: fill stage 0
    gemm_issue(0, sbase, tid, l0, n0);

    float4 acc[4][4];
    #pragma unroll
    for (int mt = 0; mt < 4; mt++)
        #pragma unroll
        for (int nt = 0; nt < 4; nt++)
            acc[mt][nt] = make_float4(0.f, 0.f, 0.f, 0.f);

    // fragment address components (stage-relative; plane base added per use)
    const uint32_t aoff = (uint32_t)((m0 + (lane & 15)) * APITCH + (lane >> 4) * 16);
    const uint32_t boff = (uint32_t)((nw0 + (lane & 7) + ((lane >> 4) << 3)) * APITCH
                        + ((lane >> 3) & 1) * 16);

    #pragma unroll 1
    for (int c = 0; c < NCHUNK; c++) {
        asm volatile("cp.async.wait_group 0;" ::: "memory");
        __syncthreads();
        if (c < NCHUNK - 1) gemm_issue(c + 1, sbase, tid, l0, n0);

        const uint32_t st = sbase + (uint32_t)(c & 1) * STG_BYTES;
        #pragma unroll
        for (int ks = 0; ks < 2; ks++) {
            const uint32_t ko = (uint32_t)(ks * 32);
            // pass 1: aH * bH
            uint32_t aH[4][4];
            #pragma unroll
            for (int mt = 0; mt < 4; mt++)
                ldsm4(aH[mt], st + aoff + (uint32_t)(mt * 16 * APITCH) + ko);
            uint32_t bH[2][4];
            #pragma unroll
            for (int nh = 0; nh < 2; nh++)
                ldsm4(bH[nh], st + 2 * PLANE + boff + (uint32_t)(nh * 16 * APITCH) + ko);
            #pragma unroll
            for (int mt = 0; mt < 4; mt++)
                #pragma unroll
                for (int nt = 0; nt < 4; nt++)
                    mma16(acc[mt][nt], aH[mt][0], aH[mt][1], aH[mt][2], aH[mt][3],
                          bH[nt >> 1][(nt & 1) * 2], bH[nt >> 1][(nt & 1) * 2 + 1]);
            // pass 2: aH * bL
            {
                uint32_t bL[2][4];
                #pragma unroll
                for (int nh = 0; nh < 2; nh++)
                    ldsm4(bL[nh], st + 3 * PLANE + boff + (uint32_t)(nh * 16 * APITCH) + ko);
                #pragma unroll
                for (int mt = 0; mt < 4; mt++)
                    #pragma unroll
                    for (int nt = 0; nt < 4; nt++)
                        mma16(acc[mt][nt], aH[mt][0], aH[mt][1], aH[mt][2], aH[mt][3],
                              bL[nt >> 1][(nt & 1) * 2], bL[nt >> 1][(nt & 1) * 2 + 1]);
            }
            // pass 3: aL * bH
            {
                uint32_t aL[4][4];
                #pragma unroll
                for (int mt = 0; mt < 4; mt++)
                    ldsm4(aL[mt], st + PLANE + aoff + (uint32_t)(mt * 16 * APITCH) + ko);
                #pragma unroll
                for (int mt = 0; mt < 4; mt++)
                    #pragma unroll
                    for (int nt = 0; nt < 4; nt++)
                        mma16(acc[mt][nt], aL[mt][0], aL[mt][1], aL[mt][2], aL[mt][3],
                              bH[nt >> 1][(nt & 1) * 2], bH[nt >> 1][(nt & 1) * 2 + 1]);
            }
        }
    }

    // epilogue: write transposed -> g_XT[b, d, l]
    const int b    = l0 >> 13;
    const int lloc = l0 & (SEQ - 1);
    #pragma unroll
    for (int mt = 0; mt < 4; mt++) {
        const int lbase = lloc + m0 + mt * 16 + g;
        #pragma unroll
        for (int nt = 0; nt < 4; nt++) {
            const int d0 = n0 + nw0 + nt * 8 + 2 * tig;
            float4 cc = acc[mt][nt];
            float* pa = g_XT + (((size_t)(b * DIM + d0)) << 13) + lbase;
            float* pb = g_XT + (((size_t)(b * DIM + d0 + 1)) << 13) + lbase;
            pa[0] = cc.x; pb[0] = cc.y;
            pa[8] = cc.z; pb[8] = cc.w;
        }
    }
}

// ---------------------------------------------------------------------------
// Kernel 3: per-(b,d) FFT convolution, in place on g_XT rows.
// Fused: fwd stage 1 reads global directly (zero-pad aware); inverse stage 1
// applies the spectral multiply; inverse final stage writes only the needed
// half straight to global.
// ---------------------------------------------------------------------------
__global__ void __launch_bounds__(512, 1)
conv_kernel() {
    extern __shared__ float2 fb[];
    float2* A  = fb;
    float2* Bu = fb + FFT_BUF;

    const int tid = threadIdx.x;
    const int d   = blockIdx.x >> 2;
    const int b   = blockIdx.x & 3;

    float2* row = (float2*)(g_XT + (((size_t)(b * DIM + d)) << 13));
    const float2* vs = g_VS + ((size_t)d << 13);

    // ---- forward FFT: stage 1 (Ns=1, no twiddle) straight from global ----
    #pragma unroll
    for (int it = 0; it < 2; it++) {
        int j = tid + it * 512;
        float2 v[8];
        #pragma unroll
        for (int r = 0; r < 8; r++)
            v[r] = (r < 4) ? row[j + r * 1024] : make_float2(0.0f, 0.0f);
        dft8<-1>(v);
        #pragma unroll
        for (int r = 0; r < 8; r++) A[SMX(j * 8 + r)] = v[r];
    }
    __syncthreads();
    fft_stage<-1>(A, Bu, 8, tid);
    fft_stage<-1>(Bu, A, 64, tid);
    fft_stage<-1>(A, Bu, 512, tid);
    fft_r2<-1>(Bu, A, tid);            // spectrum now in A

    // ---- inverse FFT: stage 1 (Ns=1) with fused spectral multiply ----
    #pragma unroll
    for (int it = 0; it < 2; it++) {
        int j = tid + it * 512;
        float2 v[8];
        #pragma unroll
        for (int r = 0; r < 8; r++) {
            int idx = j + r * 1024;
            v[r] = cmul(A[SMX(idx)], vs[idx]);
        }
        dft8<1>(v);
        #pragma unroll
        for (int r = 0; r < 8; r++) Bu[SMX(j * 8 + r)] = v[r];
    }
    __syncthreads();
    fft_stage<1>(Bu, A, 8, tid);
    fft_stage<1>(A, Bu, 64, tid);
    fft_stage<1>(Bu, A, 512, tid);

    // ---- inverse final radix-2: write the needed half straight to global ----
    const float angc2 = 6.283185307179586f / 8192.0f;
    #pragma unroll
    for (int it = 0; it < 8; it++) {
        int j = tid + it * 512;            // 0..4095
        float c, sn;
        __sincosf(angc2 * (float)j, &sn, &c);
        float2 v0 = A[SMX(j)];
        float2 v1 = cmul(A[SMX(j + 4096)], make_float2(c, sn));
        row[j] = make_float2(v0.x + v1.x, v0.y + v1.y);
    }
}

// ---------------------------------------------------------------------------
// Kernel 4: transpose g_XT (B,D,L) -> out (B,L,D)
// ---------------------------------------------------------------------------
__global__ void __launch_bounds__(256, 4)
transpose_kernel(float* __restrict__ out) {
    __shared__ float t[32][33];
    const int b  = blockIdx.z;
    const int l0 = blockIdx.x * 32;
    const int d0 = blockIdx.y * 32;
    const int tx = threadIdx.x, ty = threadIdx.y;   // 32 x 8

    const float* src = g_XT + (size_t)b * DIM * SEQ;
    #pragma unroll
    for (int i = 0; i < 4; i++)
        t[ty + i * 8][tx] = src[(size_t)(d0 + ty + i * 8) * SEQ + l0 + tx];
    __syncthreads();
    float* dst = out + (size_t)b * SEQ * DIM;
    #pragma unroll
    for (int i = 0; i < 4; i++)
        dst[(size_t)(l0 + ty + i * 8) * DIM + d0 + tx] = t[tx][ty + i * 8];
}

// ---------------------------------------------------------------------------
// launch
// ---------------------------------------------------------------------------
extern "C" void kernel_launch(void* const* d_in, const int* in_sizes, int n_in,
                              void* d_out, int out_size) {
    const float* x   = (const float*)d_in[0];
    const float* phi = (const float*)d_in[1];
    const float* Mi  = (const float*)d_in[2];
    const float* Mf  = (const float*)d_in[3];
    float* out = (float*)d_out;

    cudaFuncSetAttribute(filter_kernel, cudaFuncAttributeMaxDynamicSharedMemorySize, FFT_SMEM_BYTES);
    cudaFuncSetAttribute(conv_kernel,   cudaFuncAttributeMaxDynamicSharedMemorySize, FFT_SMEM_BYTES);
    cudaFuncSetAttribute(gemm_kernel,   cudaFuncAttributeMaxDynamicSharedMemorySize, GEMM_DYN_BYTES);

    split_x_kernel<<<(BATCH * SEQ * DIM / 4) / 256, 256>>>(x);
    split_b_kernel<<<(DIM * DIM / 2) / 256, 256>>>(Mi);
    filter_kernel<<<DIM, 512, FFT_SMEM_BYTES>>>(phi, Mf);
    gemm_kernel<<<dim3(DIM / 128, (BATCH * SEQ) / 128), 256, GEMM_DYN_BYTES>>>(0);
    conv_kernel<<<BATCH * DIM, 512, FFT_SMEM_BYTES>>>();
    transpose_kernel<<<dim3(SEQ / 32, DIM / 32, BATCH), dim3(32, 8)>>>(out);
}